// round 11
// baseline (speedup 1.0000x reference)
#include <cuda_runtime.h>
#include <cstdint>

#define BB   2
#define SS   2048
#define HIDD 1024
#define NHH  4
#define HDD  256

// Scratch (allocation-free rule -> __device__ globals)
__device__ float g_q[BB*NHH*SS*HDD];
__device__ float g_k[BB*NHH*SS*HDD];
__device__ float g_v[BB*NHH*SS*HDD];
__device__ float g_o[BB*SS*HIDD];

// ---------------------------------------------------------------------------
// helpers (base PTX ISA, works on sm_103 target)
// ---------------------------------------------------------------------------
__device__ __forceinline__ void mma168(float* c, const uint32_t* a, const uint32_t* b) {
    asm volatile(
        "mma.sync.aligned.m16n8k8.row.col.f32.tf32.tf32.f32 "
        "{%0,%1,%2,%3}, {%4,%5,%6,%7}, {%8,%9}, {%0,%1,%2,%3};"
        : "+f"(c[0]), "+f"(c[1]), "+f"(c[2]), "+f"(c[3])
        : "r"(a[0]), "r"(a[1]), "r"(a[2]), "r"(a[3]), "r"(b[0]), "r"(b[1]));
}
__device__ __forceinline__ uint32_t f2tf32(float x) {
    uint32_t u;
    asm("cvt.rna.tf32.f32 %0, %1;" : "=r"(u) : "f"(x));
    return u;
}
__device__ __forceinline__ float roundtf(float x) {
    return __uint_as_float(f2tf32(x));
}

// ===========================================================================
// GEMM kernels: tf32 mma.sync, R9 mainloop (2 CTAs/SM, no prefetch).
// ===========================================================================
#define TSTR 36

__device__ __forceinline__ void mma_mainloop(
    const float* __restrict__ A, const float* __restrict__ Bmat,
    int m0, int n0, uint32_t* As, uint32_t* Bs, float c[4][4][4])
{
    const int tid  = threadIdx.x;
    const int wid  = tid >> 5, lane = tid & 31;
    const int g    = lane >> 2, tg = lane & 3;
    const int warpM = wid >> 2, warpN = wid & 3;

#pragma unroll
    for (int mt = 0; mt < 4; mt++)
#pragma unroll
        for (int nt = 0; nt < 4; nt++)
#pragma unroll
            for (int r = 0; r < 4; r++) c[mt][nt][r] = 0.f;

    for (int kt = 0; kt < 32; kt++) {
        const int k0 = kt * 32;
        __syncthreads();
        const float* Ag = A    + (size_t)m0 * 1024 + k0;
        const float* Bg = Bmat + (size_t)n0 * 1024 + k0;
#pragma unroll
        for (int j = 0; j < 4; j++) {
            int f   = tid * 4 + j;
            int row = f >> 3;
            int cw  = (f & 7) * 4;
            float4 va = *(const float4*)(Ag + (size_t)row * 1024 + cw);
            float4 vb = *(const float4*)(Bg + (size_t)row * 1024 + cw);
            uint4 ua = make_uint4(f2tf32(va.x), f2tf32(va.y), f2tf32(va.z), f2tf32(va.w));
            uint4 ub = make_uint4(f2tf32(vb.x), f2tf32(vb.y), f2tf32(vb.z), f2tf32(vb.w));
            *(uint4*)&As[row * TSTR + cw] = ua;
            *(uint4*)&Bs[row * TSTR + cw] = ub;
        }
        __syncthreads();

#pragma unroll
        for (int ks = 0; ks < 4; ks++) {
            const int kk = ks * 8;
            uint32_t a[4][4], b[4][2];
#pragma unroll
            for (int mt = 0; mt < 4; mt++) {
                int r = warpM * 64 + mt * 16 + g;
                a[mt][0] = As[r * TSTR + kk + tg];
                a[mt][1] = As[(r + 8) * TSTR + kk + tg];
                a[mt][2] = As[r * TSTR + kk + tg + 4];
                a[mt][3] = As[(r + 8) * TSTR + kk + tg + 4];
            }
#pragma unroll
            for (int nt = 0; nt < 4; nt++) {
                int n = warpN * 32 + nt * 8 + g;
                b[nt][0] = Bs[n * TSTR + kk + tg];
                b[nt][1] = Bs[n * TSTR + kk + tg + 4];
            }
#pragma unroll
            for (int mt = 0; mt < 4; mt++)
#pragma unroll
                for (int nt = 0; nt < 4; nt++)
                    mma168(c[mt][nt], a[mt], b[nt]);
        }
    }
}

__global__ __launch_bounds__(256, 2) void qkv_mma_kernel(
    const float* __restrict__ A, const float* __restrict__ W,
    const float* __restrict__ fr, const float* __restrict__ fi)
{
    __shared__ uint32_t As[128 * TSTR];
    __shared__ uint32_t Bs[128 * TSTR];
    const int tid  = threadIdx.x;
    const int wid  = tid >> 5, lane = tid & 31;
    const int g    = lane >> 2, tg = lane & 3;
    const int warpM = wid >> 2, warpN = wid & 3;
    const int m0 = blockIdx.y * 128;
    const int n0 = blockIdx.x * 128;

    float c[4][4][4];
    mma_mainloop(A, W, m0, n0, As, Bs, c);

    // Epilogue: RoPE + scatter, PRE-ROUNDED to tf32 for the attention kernel.
    const int which = n0 >> 10;
#pragma unroll
    for (int mt = 0; mt < 4; mt++) {
#pragma unroll
        for (int half = 0; half < 2; half++) {
            int m  = m0 + warpM * 64 + mt * 16 + g + half * 8;
            int bb = m >> 11;
            int ss = m & 2047;
#pragma unroll
            for (int nt = 0; nt < 4; nt++) {
                int n = n0 + warpN * 32 + nt * 8 + tg * 2;
                int h = (n >> 8) & 3;
                int d = n & 255;
                float x0 = c[mt][nt][half * 2];
                float x1 = c[mt][nt][half * 2 + 1];
                size_t oidx = (((size_t)(bb * NHH + h)) * SS + ss) * HDD + d;
                if (which == 2) {
                    *(float2*)&g_v[oidx] = make_float2(roundtf(x0), roundtf(x1));
                } else {
                    float fre = __ldg(&fr[(size_t)ss * 128 + (d >> 1)]);
                    float fim = __ldg(&fi[(size_t)ss * 128 + (d >> 1)]);
                    float o0 = x0 * fre - x1 * fim;
                    float o1 = x0 * fim + x1 * fre;
                    float* dst = (which == 0) ? g_q : g_k;
                    *(float2*)&dst[oidx] = make_float2(roundtf(o0), roundtf(o1));
                }
            }
        }
    }
}

__global__ __launch_bounds__(256, 2) void o_mma_kernel(
    const float* __restrict__ A, const float* __restrict__ W,
    float* __restrict__ C)
{
    __shared__ uint32_t As[128 * TSTR];
    __shared__ uint32_t Bs[128 * TSTR];
    const int tid  = threadIdx.x;
    const int wid  = tid >> 5, lane = tid & 31;
    const int g    = lane >> 2, tg = lane & 3;
    const int warpM = wid >> 2, warpN = wid & 3;
    const int m0 = blockIdx.y * 128;
    const int n0 = blockIdx.x * 128;

    float c[4][4][4];
    mma_mainloop(A, W, m0, n0, As, Bs, c);

#pragma unroll
    for (int mt = 0; mt < 4; mt++) {
#pragma unroll
        for (int half = 0; half < 2; half++) {
            int m = m0 + warpM * 64 + mt * 16 + g + half * 8;
#pragma unroll
            for (int nt = 0; nt < 4; nt++) {
                int n = n0 + warpN * 32 + nt * 8 + tg * 2;
                *(float2*)&C[(size_t)m * 1024 + n] =
                    make_float2(c[mt][nt][half * 2], c[mt][nt][half * 2 + 1]);
            }
        }
    }
}

// ===========================================================================
// Kernel 2: tensor-core causal flash attention, occupancy-2 version.
// 32 q-rows x 32 kv-rows per iter; smem ~106KB -> 2 CTAs/SM.
// 8 warps = 2 (row, 16 each) x 4 (col). S warp-tile 16x8; PV 16x64.
// ===========================================================================
#define QT   32
#define QSTR 260
#define VSTR 264
#define PSTR 36

extern __shared__ uint32_t attn_sm[];

__global__ __launch_bounds__(256, 2) void attn_mma_kernel(
    const float* __restrict__ qg, const float* __restrict__ kg,
    const float* __restrict__ vg, float* __restrict__ og)
{
    uint32_t* Qs = attn_sm;                  // [32][QSTR]
    uint32_t* Ks = Qs + QT * QSTR;           // [32][QSTR]
    uint32_t* Vs = Ks + QT * QSTR;           // [32][VSTR]
    uint32_t* Ps = Vs + QT * VSTR;           // [32][PSTR]
    float* mS   = (float*)(Ps + QT * PSTR);  // [32]
    float* lS   = mS + 32;                   // [32]
    float* pmax = lS + 32;                   // [4][32]
    float* psum = pmax + 128;                // [4][32]

    const int tid  = threadIdx.x;
    const int wid  = tid >> 5, lane = tid & 31;
    const int g    = lane >> 2, tg = lane & 3;
    const int warpRow = wid >> 2;            // 0..1
    const int warpCol = wid & 3;             // 0..3

    const int qt  = gridDim.x - 1 - blockIdx.x;   // heavy CTAs first
    const int q0  = qt * QT;
    const int h   = blockIdx.y;
    const int b   = blockIdx.z;
    const size_t base = ((size_t)(b * NHH + h)) * SS * HDD;
    const float scale = 0.0625f;                  // exact power of 2

    // load Q tile (scale exact -> stays tf32); 32x256 floats, 8 f4/thread
#pragma unroll
    for (int it = 0; it < 8; it++) {
        int f   = tid + it * 256;
        int row = f >> 6;
        int c4  = (f & 63) * 4;
        float4 v = *(const float4*)&qg[base + (size_t)(q0 + row) * HDD + c4];
        float4 w = make_float4(v.x * scale, v.y * scale, v.z * scale, v.w * scale);
        *(float4*)((float*)Qs + row * QSTR + c4) = w;
    }
    if (tid < 32) { mS[tid] = -1e30f; lS[tid] = 0.f; }

    float o[8][4];
#pragma unroll
    for (int nt = 0; nt < 8; nt++)
#pragma unroll
        for (int r = 0; r < 4; r++) o[nt][r] = 0.f;

    const int rg = warpRow * 16 + g;         // first row this lane owns

    const int nkb = qt + 1;
    for (int kbi = 0; kbi < nkb; kbi++) {
        const int k0 = kbi * QT;
        __syncthreads();                     // prev iter done reading Ks/Vs/Ps

        // K,V tile copy (pre-rounded -> raw float4); 32x256 each
#pragma unroll
        for (int it = 0; it < 8; it++) {
            int f   = tid + it * 256;
            int row = f >> 6;
            int c4  = (f & 63) * 4;
            size_t gi = base + (size_t)(k0 + row) * HDD + c4;
            *(uint4*)&Ks[row * QSTR + c4] = *(const uint4*)&kg[gi];
            *(uint4*)&Vs[row * VSTR + c4] = *(const uint4*)&vg[gi];
        }
        __syncthreads();

        // ---- S = Q K^T : warp tile 16 x 8, two accumulator chains ----
        float sA[4], sB[4];
#pragma unroll
        for (int r = 0; r < 4; r++) { sA[r] = 0.f; sB[r] = 0.f; }
        const int n8 = warpCol * 8 + g;      // this warp's S col block row in K

#pragma unroll 4
        for (int kk = 0; kk < 256; kk += 16) {
            uint32_t a0[4], a1[4], b0[2], b1[2];
            a0[0] = Qs[rg * QSTR + kk + tg];
            a0[1] = Qs[(rg + 8) * QSTR + kk + tg];
            a0[2] = Qs[rg * QSTR + kk + tg + 4];
            a0[3] = Qs[(rg + 8) * QSTR + kk + tg + 4];
            b0[0] = Ks[n8 * QSTR + kk + tg];
            b0[1] = Ks[n8 * QSTR + kk + tg + 4];
            a1[0] = Qs[rg * QSTR + kk + 8 + tg];
            a1[1] = Qs[(rg + 8) * QSTR + kk + 8 + tg];
            a1[2] = Qs[rg * QSTR + kk + 8 + tg + 4];
            a1[3] = Qs[(rg + 8) * QSTR + kk + 8 + tg + 4];
            b1[0] = Ks[n8 * QSTR + kk + 8 + tg];
            b1[1] = Ks[n8 * QSTR + kk + 8 + tg + 4];
            mma168(sA, a0, b0);
            mma168(sB, a1, b1);
        }
        float s[4];
#pragma unroll
        for (int r = 0; r < 4; r++) s[r] = sA[r] + sB[r];

        // causal mask on diagonal tile
        if (kbi == qt) {
#pragma unroll
            for (int r = 0; r < 4; r++) {
                int row = q0 + rg + ((r & 2) ? 8 : 0);
                int col = k0 + warpCol * 8 + 2 * tg + (r & 1);
                if (col > row) s[r] = -1e30f;
            }
        }

        // partial row max within this warp's 8 cols
        float mx0 = fmaxf(s[0], s[1]);
        float mx1 = fmaxf(s[2], s[3]);
        mx0 = fmaxf(mx0, __shfl_xor_sync(0xffffffffu, mx0, 1));
        mx0 = fmaxf(mx0, __shfl_xor_sync(0xffffffffu, mx0, 2));
        mx1 = fmaxf(mx1, __shfl_xor_sync(0xffffffffu, mx1, 1));
        mx1 = fmaxf(mx1, __shfl_xor_sync(0xffffffffu, mx1, 2));
        if (tg == 0) {
            pmax[warpCol * 32 + rg]     = mx0;
            pmax[warpCol * 32 + rg + 8] = mx1;
        }
        __syncthreads();

        float m0old = mS[rg], m1old = mS[rg + 8];
        float m0 = fmaxf(fmaxf(pmax[rg],      pmax[32 + rg]),
                         fmaxf(pmax[64 + rg], pmax[96 + rg]));
        float m1 = fmaxf(fmaxf(pmax[rg + 8],      pmax[32 + rg + 8]),
                         fmaxf(pmax[64 + rg + 8], pmax[96 + rg + 8]));
        m0 = fmaxf(m0old, m0);
        m1 = fmaxf(m1old, m1);
        float resc0 = __expf(m0old - m0);
        float resc1 = __expf(m1old - m1);

        const int cl = warpCol * 8 + 2 * tg;
        float p0 = __expf(s[0] - m0);
        float p1 = __expf(s[1] - m0);
        float p2 = __expf(s[2] - m1);
        float p3 = __expf(s[3] - m1);
        float sum0 = p0 + p1;
        float sum1 = p2 + p3;
        Ps[rg * PSTR + cl]           = f2tf32(p0);
        Ps[rg * PSTR + cl + 1]       = f2tf32(p1);
        Ps[(rg + 8) * PSTR + cl]     = f2tf32(p2);
        Ps[(rg + 8) * PSTR + cl + 1] = f2tf32(p3);
        sum0 += __shfl_xor_sync(0xffffffffu, sum0, 1);
        sum0 += __shfl_xor_sync(0xffffffffu, sum0, 2);
        sum1 += __shfl_xor_sync(0xffffffffu, sum1, 1);
        sum1 += __shfl_xor_sync(0xffffffffu, sum1, 2);
        if (tg == 0) {
            psum[warpCol * 32 + rg]     = sum0;
            psum[warpCol * 32 + rg + 8] = sum1;
        }
        __syncthreads();

        // stats update (one owner per row)
        if (warpCol == 0 && tg == 0) {
            lS[rg]     = lS[rg] * resc0
                       + psum[rg] + psum[32 + rg] + psum[64 + rg] + psum[96 + rg];
            lS[rg + 8] = lS[rg + 8] * resc1
                       + psum[rg + 8] + psum[32 + rg + 8] + psum[64 + rg + 8] + psum[96 + rg + 8];
            mS[rg]     = m0;
            mS[rg + 8] = m1;
        }

        // ---- O = O*resc + P V : warp tile 16 x 64 ----
#pragma unroll
        for (int nt = 0; nt < 8; nt++) {
            o[nt][0] *= resc0; o[nt][1] *= resc0;
            o[nt][2] *= resc1; o[nt][3] *= resc1;
        }
#pragma unroll
        for (int kk8 = 0; kk8 < 4; kk8++) {
            const int kk = kk8 * 8;
            uint32_t a[4];
            a[0] = Ps[rg * PSTR + kk + tg];
            a[1] = Ps[(rg + 8) * PSTR + kk + tg];
            a[2] = Ps[rg * PSTR + kk + tg + 4];
            a[3] = Ps[(rg + 8) * PSTR + kk + tg + 4];
#pragma unroll
            for (int nt = 0; nt < 8; nt++) {
                int n = warpCol * 64 + nt * 8 + g;
                uint32_t bb2[2];
                bb2[0] = Vs[(kk + tg) * VSTR + n];
                bb2[1] = Vs[(kk + tg + 4) * VSTR + n];
                mma168(o[nt], a, bb2);
            }
        }
    }
    __syncthreads();

    // epilogue: normalize + write
    float linv0 = 1.f / lS[rg];
    float linv1 = 1.f / lS[rg + 8];
    size_t ob0 = ((size_t)b * SS + (q0 + rg))     * HIDD + h * HDD;
    size_t ob1 = ((size_t)b * SS + (q0 + rg + 8)) * HIDD + h * HDD;
#pragma unroll
    for (int nt = 0; nt < 8; nt++) {
        int col = warpCol * 64 + nt * 8 + 2 * tg;
        *(float2*)&og[ob0 + col] = make_float2(o[nt][0] * linv0, o[nt][1] * linv0);
        *(float2*)&og[ob1 + col] = make_float2(o[nt][2] * linv1, o[nt][3] * linv1);
    }
}

// ---------------------------------------------------------------------------
extern "C" void kernel_launch(void* const* d_in, const int* in_sizes, int n_in,
                              void* d_out, int out_size)
{
    const float* hidden = (const float*)d_in[0];
    const float* fr     = (const float*)d_in[1];
    const float* fi     = (const float*)d_in[2];
    // d_in[3] = mask (causal handled analytically)
    const float* Wqkv   = (const float*)d_in[4];
    const float* Wo     = (const float*)d_in[5];
    float* out = (float*)d_out;

    float *qb, *kb, *vb, *ob;
    cudaGetSymbolAddress((void**)&qb, g_q);
    cudaGetSymbolAddress((void**)&kb, g_k);
    cudaGetSymbolAddress((void**)&vb, g_v);
    cudaGetSymbolAddress((void**)&ob, g_o);

    // 1) QKV + RoPE on tf32 mma.sync (occ 2)
    dim3 g1(3072 / 128, 4096 / 128);
    qkv_mma_kernel<<<g1, 256>>>(hidden, Wqkv, fr, fi);

    // 2) tensor-core flash attention, occ 2
    const int asmB = (QT * QSTR + QT * QSTR + QT * VSTR + QT * PSTR + 32 * 2 + 128 * 2) * 4;
    cudaFuncSetAttribute(attn_mma_kernel, cudaFuncAttributeMaxDynamicSharedMemorySize, asmB);
    dim3 g2(SS / QT, NHH, BB);
    attn_mma_kernel<<<g2, 256, asmB>>>(qb, kb, vb, ob);

    // 3) output projection on tf32 mma.sync (occ 2)
    dim3 g3(1024 / 128, 4096 / 128);
    o_mma_kernel<<<g3, 256>>>(ob, Wo, out);
}

// round 12
// speedup vs baseline: 1.1636x; 1.1636x over previous
#include <cuda_runtime.h>
#include <cstdint>

#define BB   2
#define SS   2048
#define HIDD 1024
#define NHH  4
#define HDD  256

// Scratch (allocation-free rule -> __device__ globals)
__device__ float g_q[BB*NHH*SS*HDD];
__device__ float g_k[BB*NHH*SS*HDD];
__device__ float g_v[BB*NHH*SS*HDD];
__device__ float g_o[BB*SS*HIDD];

// ---------------------------------------------------------------------------
// helpers (base PTX ISA, works on sm_103 target)
// ---------------------------------------------------------------------------
__device__ __forceinline__ void mma168(float* c, const uint32_t* a, const uint32_t* b) {
    asm volatile(
        "mma.sync.aligned.m16n8k8.row.col.f32.tf32.tf32.f32 "
        "{%0,%1,%2,%3}, {%4,%5,%6,%7}, {%8,%9}, {%0,%1,%2,%3};"
        : "+f"(c[0]), "+f"(c[1]), "+f"(c[2]), "+f"(c[3])
        : "r"(a[0]), "r"(a[1]), "r"(a[2]), "r"(a[3]), "r"(b[0]), "r"(b[1]));
}
__device__ __forceinline__ uint32_t f2tf32(float x) {
    uint32_t u;
    asm("cvt.rna.tf32.f32 %0, %1;" : "=r"(u) : "f"(x));
    return u;
}
__device__ __forceinline__ float roundtf(float x) {
    return __uint_as_float(f2tf32(x));
}
#define PAIR_BAR(id) asm volatile("bar.sync %0, 64;" :: "r"(id) : "memory")

// ===========================================================================
// GEMM kernels: tf32 mma.sync, R9 mainloop (2 CTAs/SM, no prefetch).
// ===========================================================================
#define TSTR 36

__device__ __forceinline__ void mma_mainloop(
    const float* __restrict__ A, const float* __restrict__ Bmat,
    int m0, int n0, uint32_t* As, uint32_t* Bs, float c[4][4][4])
{
    const int tid  = threadIdx.x;
    const int wid  = tid >> 5, lane = tid & 31;
    const int g    = lane >> 2, tg = lane & 3;
    const int warpM = wid >> 2, warpN = wid & 3;

#pragma unroll
    for (int mt = 0; mt < 4; mt++)
#pragma unroll
        for (int nt = 0; nt < 4; nt++)
#pragma unroll
            for (int r = 0; r < 4; r++) c[mt][nt][r] = 0.f;

    for (int kt = 0; kt < 32; kt++) {
        const int k0 = kt * 32;
        __syncthreads();
        const float* Ag = A    + (size_t)m0 * 1024 + k0;
        const float* Bg = Bmat + (size_t)n0 * 1024 + k0;
#pragma unroll
        for (int j = 0; j < 4; j++) {
            int f   = tid * 4 + j;
            int row = f >> 3;
            int cw  = (f & 7) * 4;
            float4 va = *(const float4*)(Ag + (size_t)row * 1024 + cw);
            float4 vb = *(const float4*)(Bg + (size_t)row * 1024 + cw);
            uint4 ua = make_uint4(f2tf32(va.x), f2tf32(va.y), f2tf32(va.z), f2tf32(va.w));
            uint4 ub = make_uint4(f2tf32(vb.x), f2tf32(vb.y), f2tf32(vb.z), f2tf32(vb.w));
            *(uint4*)&As[row * TSTR + cw] = ua;
            *(uint4*)&Bs[row * TSTR + cw] = ub;
        }
        __syncthreads();

#pragma unroll
        for (int ks = 0; ks < 4; ks++) {
            const int kk = ks * 8;
            uint32_t a[4][4], b[4][2];
#pragma unroll
            for (int mt = 0; mt < 4; mt++) {
                int r = warpM * 64 + mt * 16 + g;
                a[mt][0] = As[r * TSTR + kk + tg];
                a[mt][1] = As[(r + 8) * TSTR + kk + tg];
                a[mt][2] = As[r * TSTR + kk + tg + 4];
                a[mt][3] = As[(r + 8) * TSTR + kk + tg + 4];
            }
#pragma unroll
            for (int nt = 0; nt < 4; nt++) {
                int n = warpN * 32 + nt * 8 + g;
                b[nt][0] = Bs[n * TSTR + kk + tg];
                b[nt][1] = Bs[n * TSTR + kk + tg + 4];
            }
#pragma unroll
            for (int mt = 0; mt < 4; mt++)
#pragma unroll
                for (int nt = 0; nt < 4; nt++)
                    mma168(c[mt][nt], a[mt], b[nt]);
        }
    }
}

__global__ __launch_bounds__(256, 2) void qkv_mma_kernel(
    const float* __restrict__ A, const float* __restrict__ W,
    const float* __restrict__ fr, const float* __restrict__ fi)
{
    __shared__ uint32_t As[128 * TSTR];
    __shared__ uint32_t Bs[128 * TSTR];
    const int tid  = threadIdx.x;
    const int wid  = tid >> 5, lane = tid & 31;
    const int g    = lane >> 2, tg = lane & 3;
    const int warpM = wid >> 2, warpN = wid & 3;
    const int m0 = blockIdx.y * 128;
    const int n0 = blockIdx.x * 128;

    float c[4][4][4];
    mma_mainloop(A, W, m0, n0, As, Bs, c);

    // Epilogue: RoPE + scatter, PRE-ROUNDED to tf32 for the attention kernel.
    const int which = n0 >> 10;
#pragma unroll
    for (int mt = 0; mt < 4; mt++) {
#pragma unroll
        for (int half = 0; half < 2; half++) {
            int m  = m0 + warpM * 64 + mt * 16 + g + half * 8;
            int bb = m >> 11;
            int ss = m & 2047;
#pragma unroll
            for (int nt = 0; nt < 4; nt++) {
                int n = n0 + warpN * 32 + nt * 8 + tg * 2;
                int h = (n >> 8) & 3;
                int d = n & 255;
                float x0 = c[mt][nt][half * 2];
                float x1 = c[mt][nt][half * 2 + 1];
                size_t oidx = (((size_t)(bb * NHH + h)) * SS + ss) * HDD + d;
                if (which == 2) {
                    *(float2*)&g_v[oidx] = make_float2(roundtf(x0), roundtf(x1));
                } else {
                    float fre = __ldg(&fr[(size_t)ss * 128 + (d >> 1)]);
                    float fim = __ldg(&fi[(size_t)ss * 128 + (d >> 1)]);
                    float o0 = x0 * fre - x1 * fim;
                    float o1 = x0 * fim + x1 * fre;
                    float* dst = (which == 0) ? g_q : g_k;
                    *(float2*)&dst[oidx] = make_float2(roundtf(o0), roundtf(o1));
                }
            }
        }
    }
}

__global__ __launch_bounds__(256, 2) void o_mma_kernel(
    const float* __restrict__ A, const float* __restrict__ W,
    float* __restrict__ C)
{
    __shared__ uint32_t As[128 * TSTR];
    __shared__ uint32_t Bs[128 * TSTR];
    const int tid  = threadIdx.x;
    const int wid  = tid >> 5, lane = tid & 31;
    const int g    = lane >> 2, tg = lane & 3;
    const int warpM = wid >> 2, warpN = wid & 3;
    const int m0 = blockIdx.y * 128;
    const int n0 = blockIdx.x * 128;

    float c[4][4][4];
    mma_mainloop(A, W, m0, n0, As, Bs, c);

#pragma unroll
    for (int mt = 0; mt < 4; mt++) {
#pragma unroll
        for (int half = 0; half < 2; half++) {
            int m = m0 + warpM * 64 + mt * 16 + g + half * 8;
#pragma unroll
            for (int nt = 0; nt < 4; nt++) {
                int n = n0 + warpN * 32 + nt * 8 + tg * 2;
                *(float2*)&C[(size_t)m * 1024 + n] =
                    make_float2(c[mt][nt][half * 2], c[mt][nt][half * 2 + 1]);
            }
        }
    }
}

// ===========================================================================
// Kernel 2: tensor-core causal flash attention (R9 64x64 structure) with
// single-exchange softmax + named pair barriers.
// 8 warps = 4 row-slabs (16 rows) x 2 col-halves (32). Pair = (wid&~1, wid|1).
// ===========================================================================
#define QSTR 260
#define VSTR 264
#define PSTR 68

extern __shared__ uint32_t attn_sm[];

__global__ __launch_bounds__(256, 1) void attn_mma_kernel(
    const float* __restrict__ qg, const float* __restrict__ kg,
    const float* __restrict__ vg, float* __restrict__ og)
{
    uint32_t* Qs = attn_sm;                 // [64][QSTR]
    uint32_t* Ks = Qs + 64 * QSTR;          // [64][QSTR]
    uint32_t* Vs = Ks + 64 * QSTR;          // [64][VSTR]
    uint32_t* Ps = Vs + 64 * VSTR;          // [64][PSTR]
    float* mS   = (float*)(Ps + 64 * PSTR); // [64]
    float* lS   = mS + 64;                  // [64]
    float* pmax = lS + 64;                  // [2][64]
    float* psum = pmax + 128;               // [2][64]

    const int tid  = threadIdx.x;
    const int wid  = tid >> 5, lane = tid & 31;
    const int g    = lane >> 2, tg = lane & 3;
    const int warpRow = wid >> 1;           // 0..3
    const int warpCol = wid & 1;            // 0..1
    const int barid   = warpRow + 1;        // named barrier per pair

    const int qt  = gridDim.x - 1 - blockIdx.x;   // heavy CTAs first
    const int q0  = qt * 64;
    const int h   = blockIdx.y;
    const int b   = blockIdx.z;
    const size_t base = ((size_t)(b * NHH + h)) * SS * HDD;
    const float scale = 0.0625f;                  // exact power of 2

    // load Q tile (scale exact -> stays tf32)
#pragma unroll
    for (int it = 0; it < 16; it++) {
        int f   = tid + it * 256;
        int row = f >> 6;
        int c4  = (f & 63) * 4;
        float4 v = *(const float4*)&qg[base + (size_t)(q0 + row) * HDD + c4];
        float4 w = make_float4(v.x * scale, v.y * scale, v.z * scale, v.w * scale);
        *(float4*)((float*)Qs + row * QSTR + c4) = w;
    }
    if (tid < 64) { mS[tid] = -1e30f; lS[tid] = 0.f; }

    float o[16][4];
#pragma unroll
    for (int nt = 0; nt < 16; nt++)
#pragma unroll
        for (int r = 0; r < 4; r++) o[nt][r] = 0.f;

    const int rg = warpRow * 16 + g;

    const int nkb = qt + 1;
    for (int kbi = 0; kbi < nkb; kbi++) {
        const int k0 = kbi * 64;
        __syncthreads();                    // all warps done with prev Ks/Vs/Ps

        // K,V tile copy (pre-rounded -> raw float4)
#pragma unroll
        for (int it = 0; it < 16; it++) {
            int f   = tid + it * 256;
            int row = f >> 6;
            int c4  = (f & 63) * 4;
            size_t gi = base + (size_t)(k0 + row) * HDD + c4;
            *(uint4*)&Ks[row * QSTR + c4] = *(const uint4*)&kg[gi];
            *(uint4*)&Vs[row * VSTR + c4] = *(const uint4*)&vg[gi];
        }
        __syncthreads();

        // ---- S = Q K^T : warp tile 16 x 32 ----
        float s[4][4];
#pragma unroll
        for (int nt = 0; nt < 4; nt++)
#pragma unroll
            for (int r = 0; r < 4; r++) s[nt][r] = 0.f;

#pragma unroll 4
        for (int kk = 0; kk < 256; kk += 8) {
            uint32_t a[4];
            a[0] = Qs[rg * QSTR + kk + tg];
            a[1] = Qs[(rg + 8) * QSTR + kk + tg];
            a[2] = Qs[rg * QSTR + kk + tg + 4];
            a[3] = Qs[(rg + 8) * QSTR + kk + tg + 4];
#pragma unroll
            for (int nt = 0; nt < 4; nt++) {
                int n = warpCol * 32 + nt * 8 + g;
                uint32_t bb2[2];
                bb2[0] = Ks[n * QSTR + kk + tg];
                bb2[1] = Ks[n * QSTR + kk + tg + 4];
                mma168(s[nt], a, bb2);
            }
        }

        // causal mask on diagonal tile
        if (kbi == qt) {
#pragma unroll
            for (int nt = 0; nt < 4; nt++) {
#pragma unroll
                for (int r = 0; r < 4; r++) {
                    int row = q0 + rg + ((r & 2) ? 8 : 0);
                    int col = k0 + warpCol * 32 + nt * 8 + 2 * tg + (r & 1);
                    if (col > row) s[nt][r] = -1e30f;
                }
            }
        }

        // ---- single-exchange online softmax ----
        // in-warp partial max over this warp's 32 cols (rows rg, rg+8)
        float mx0 = -1e30f, mx1 = -1e30f;
#pragma unroll
        for (int nt = 0; nt < 4; nt++) {
            mx0 = fmaxf(mx0, fmaxf(s[nt][0], s[nt][1]));
            mx1 = fmaxf(mx1, fmaxf(s[nt][2], s[nt][3]));
        }
        mx0 = fmaxf(mx0, __shfl_xor_sync(0xffffffffu, mx0, 1));
        mx0 = fmaxf(mx0, __shfl_xor_sync(0xffffffffu, mx0, 2));
        mx1 = fmaxf(mx1, __shfl_xor_sync(0xffffffffu, mx1, 1));
        mx1 = fmaxf(mx1, __shfl_xor_sync(0xffffffffu, mx1, 2));

        // p = exp(s - own partial max), partial sums
        float p[4][4];
        float sum0 = 0.f, sum1 = 0.f;
#pragma unroll
        for (int nt = 0; nt < 4; nt++) {
            p[nt][0] = __expf(s[nt][0] - mx0);
            p[nt][1] = __expf(s[nt][1] - mx0);
            p[nt][2] = __expf(s[nt][2] - mx1);
            p[nt][3] = __expf(s[nt][3] - mx1);
            sum0 += p[nt][0] + p[nt][1];
            sum1 += p[nt][2] + p[nt][3];
        }
        sum0 += __shfl_xor_sync(0xffffffffu, sum0, 1);
        sum0 += __shfl_xor_sync(0xffffffffu, sum0, 2);
        sum1 += __shfl_xor_sync(0xffffffffu, sum1, 1);
        sum1 += __shfl_xor_sync(0xffffffffu, sum1, 2);
        if (tg == 0) {
            pmax[warpCol * 64 + rg]     = mx0;
            pmax[warpCol * 64 + rg + 8] = mx1;
            psum[warpCol * 64 + rg]     = sum0;
            psum[warpCol * 64 + rg + 8] = sum1;
        }
        PAIR_BAR(barid);                    // exchange (mx, sum) within pair

        const int oc = warpCol ^ 1;
        float mxo0 = pmax[oc * 64 + rg],     sumo0 = psum[oc * 64 + rg];
        float mxo1 = pmax[oc * 64 + rg + 8], sumo1 = psum[oc * 64 + rg + 8];

        float m0old = mS[rg], m1old = mS[rg + 8];
        float m0 = fmaxf(m0old, fmaxf(mx0, mxo0));
        float m1 = fmaxf(m1old, fmaxf(mx1, mxo1));
        float resc0 = __expf(m0old - m0);
        float resc1 = __expf(m1old - m1);
        float f0 = __expf(mx0 - m0);        // scale own p's to global max
        float f1 = __expf(mx1 - m1);

        // store P scaled to global max
        const int cl = warpCol * 32 + 2 * tg;
#pragma unroll
        for (int nt = 0; nt < 4; nt++) {
            Ps[rg * PSTR + cl + nt * 8]           = f2tf32(p[nt][0] * f0);
            Ps[rg * PSTR + cl + nt * 8 + 1]       = f2tf32(p[nt][1] * f0);
            Ps[(rg + 8) * PSTR + cl + nt * 8]     = f2tf32(p[nt][2] * f1);
            Ps[(rg + 8) * PSTR + cl + nt * 8 + 1] = f2tf32(p[nt][3] * f1);
        }

        // stats update (one owner per row; both warps computed identical m,l)
        if (warpCol == 0 && tg == 0) {
            lS[rg]     = lS[rg]     * resc0 + sum0 * f0 + sumo0 * __expf(mxo0 - m0);
            lS[rg + 8] = lS[rg + 8] * resc1 + sum1 * f1 + sumo1 * __expf(mxo1 - m1);
            mS[rg]     = m0;
            mS[rg + 8] = m1;
        }
        PAIR_BAR(barid);                    // P (and stats) visible within pair

        // ---- O = O*resc + P V : warp tile 16 x 128 ----
#pragma unroll
        for (int nt = 0; nt < 16; nt++) {
            o[nt][0] *= resc0; o[nt][1] *= resc0;
            o[nt][2] *= resc1; o[nt][3] *= resc1;
        }
#pragma unroll
        for (int kk8 = 0; kk8 < 8; kk8++) {
            const int kk = kk8 * 8;
            uint32_t a[4];
            a[0] = Ps[rg * PSTR + kk + tg];
            a[1] = Ps[(rg + 8) * PSTR + kk + tg];
            a[2] = Ps[rg * PSTR + kk + tg + 4];
            a[3] = Ps[(rg + 8) * PSTR + kk + tg + 4];
#pragma unroll
            for (int nt = 0; nt < 16; nt++) {
                int n = warpCol * 128 + nt * 8 + g;
                uint32_t bb2[2];
                bb2[0] = Vs[(kk + tg) * VSTR + n];
                bb2[1] = Vs[(kk + tg + 4) * VSTR + n];
                mma168(o[nt], a, bb2);
            }
        }
    }
    __syncthreads();

    // epilogue: normalize + write (pre-round for the O-projection's tf32 GEMM)
    float linv0 = 1.f / lS[rg];
    float linv1 = 1.f / lS[rg + 8];
    size_t ob0 = ((size_t)b * SS + (q0 + rg))     * HIDD + h * HDD;
    size_t ob1 = ((size_t)b * SS + (q0 + rg + 8)) * HIDD + h * HDD;
#pragma unroll
    for (int nt = 0; nt < 16; nt++) {
        int col = warpCol * 128 + nt * 8 + 2 * tg;
        *(float2*)&og[ob0 + col] = make_float2(o[nt][0] * linv0, o[nt][1] * linv0);
        *(float2*)&og[ob1 + col] = make_float2(o[nt][2] * linv1, o[nt][3] * linv1);
    }
}

// ---------------------------------------------------------------------------
extern "C" void kernel_launch(void* const* d_in, const int* in_sizes, int n_in,
                              void* d_out, int out_size)
{
    const float* hidden = (const float*)d_in[0];
    const float* fr     = (const float*)d_in[1];
    const float* fi     = (const float*)d_in[2];
    // d_in[3] = mask (causal handled analytically)
    const float* Wqkv   = (const float*)d_in[4];
    const float* Wo     = (const float*)d_in[5];
    float* out = (float*)d_out;

    float *qb, *kb, *vb, *ob;
    cudaGetSymbolAddress((void**)&qb, g_q);
    cudaGetSymbolAddress((void**)&kb, g_k);
    cudaGetSymbolAddress((void**)&vb, g_v);
    cudaGetSymbolAddress((void**)&ob, g_o);

    // 1) QKV + RoPE on tf32 mma.sync (occ 2)
    dim3 g1(3072 / 128, 4096 / 128);
    qkv_mma_kernel<<<g1, 256>>>(hidden, Wqkv, fr, fi);

    // 2) tensor-core flash attention (64x64, pair barriers)
    const int asmB = (64 * QSTR + 64 * QSTR + 64 * VSTR + 64 * PSTR + 64 * 2 + 128 * 2) * 4;
    cudaFuncSetAttribute(attn_mma_kernel, cudaFuncAttributeMaxDynamicSharedMemorySize, asmB);
    dim3 g2(SS / 64, NHH, BB);
    attn_mma_kernel<<<g2, 256, asmB>>>(qb, kb, vb, ob);

    // 3) output projection on tf32 mma.sync (occ 2)
    dim3 g3(1024 / 128, 4096 / 128);
    o_mma_kernel<<<g3, 256>>>(ob, Wo, out);
}